// round 11
// baseline (speedup 1.0000x reference)
#include <cuda_runtime.h>

// ExponentialGlobalConv: out[b,m,c] = DX * sum_n x[b,n] * exp(-|n-m|*DX/w_c) / (2 w_c)
// Uniform grid => separable exponential kernel => fwd+bwd IIR scan.
// R11 = minimum-latency composition of all proven pieces:
//  - direct broadcast LDG.128 for own chunk + both halo chunks (issued
//    back-to-back before any math: DRAM latency paid once, max MLP)
//  - ONE __syncthreads; smem carries only chunk end-sums (2KB)
//  - in-place fwd chain (no Floc array); bwd pass recovers
//    x_k = ax[k]-r*ax[k-1] and forms t_k = r*F_{k-1}+B_k directly
//  - combine adds s*r^{k+1} / u*r^{32-k} via 4 interleaved *r^4 chains
// Seeds s,u = 8-term dot products over neighbor end-sums (hop r^32).
// Halo truncation (HALOC=8 chunks) => rel_err ~1.9e-4 << 1e-3.

#define NCH   32
#define NG    2048
#define NB    32
#define DXC   0.08f
#define CL    32
#define HALOC 8                   // halo chunks per side
#define OUTC  8                   // output chunks per block
#define NWARP 8
#define NTHREADS (NWARP * 32)     // 256
#define BPB   8                   // blocks per batch row
#define NGC   (NG / CL)           // 64 global chunks per row

__global__ __launch_bounds__(NTHREADS, 3)
void egc_kernel(const float* __restrict__ x,
                const float* __restrict__ eta,
                float* __restrict__ out)
{
    __shared__ float ef[16][32];   // fwd end-sums, window chunks 0..15
    __shared__ float eb[16][32];   // bwd end-sums, window chunks 8..23 (idx wc-8)

    const int tid  = threadIdx.x;
    const int lane = tid & 31;              // channel
    const int w    = tid >> 5;              // warp 0..7
    const int b    = blockIdx.x >> 3;       // batch row
    const int q    = blockIdx.x & 7;        // eighth of grid dim
    const float* xrow = x + (size_t)b * NG;
    const int baseg = q * OUTC - HALOC;     // global chunk at window wc=0

    // ---- issue ALL loads up front (broadcast LDG.128, max MLP) ----
    float ax[CL];                           // own chunk (window 8+w, global q*8+w)
    {
        const float4* pa = reinterpret_cast<const float4*>(xrow + (size_t)(q * OUTC + w) * CL);
        #pragma unroll
        for (int i = 0; i < 8; i++) reinterpret_cast<float4*>(ax)[i] = pa[i];
    }
    const int fh_gc = baseg + w;            // fwd halo chunk (window w)
    const int bh_gc = baseg + 16 + w;       // bwd halo chunk (window 16+w)
    const bool fh_ok = (fh_gc >= 0);        // left edge only
    const bool bh_ok = (bh_gc < NGC);       // right edge only
    float4 FH[8], BH[8];
    {
        const float4* pf = reinterpret_cast<const float4*>(xrow + (size_t)(fh_ok ? fh_gc : 0) * CL);
        const float4* pb = reinterpret_cast<const float4*>(xrow + (size_t)(bh_ok ? bh_gc : 0) * CL);
        #pragma unroll
        for (int i = 0; i < 8; i++) { FH[i] = pf[i]; BH[i] = pb[i]; }
    }

    // ---- per-channel params (MUFU under LDG shadow) ----
    const float e     = eta[lane];
    const float sig   = 1.0f / (1.0f + __expf(-e));
    const float wid   = 0.1f + 4.9f * sig;
    const float r     = __expf(-DXC / wid);
    const float scale = DXC / (2.0f * wid);
    const float r2 = r * r, r3 = r2 * r, r4 = r2 * r2;
    const float r8 = r4 * r4, r16 = r8 * r8;
    const float rL = r16 * r16;             // r^32

    const float* fhx = reinterpret_cast<const float*>(FH);
    const float* bhx = reinterpret_cast<const float*>(BH);

    // ---- pre-scale own chunk ----
    #pragma unroll
    for (int k = 0; k < CL; k++) ax[k] *= scale;

    // ---- pass 1: fwd chain IN PLACE + fwd-halo end-scan (2 chains) ----
    {
        float F = 0.f, E = 0.f;
        #pragma unroll
        for (int k = 0; k < CL; k++) {
            F = fmaf(r, F, ax[k]); ax[k] = F;    // ax[k] := F_k (scaled)
            E = fmaf(r, E, fhx[k]);
        }
        ef[HALOC + w][lane] = F;                 // own fwd end
        ef[w][lane] = fh_ok ? E * scale : 0.f;   // fwd halo end
    }

    // ---- pass 2: bwd chain via x_k = ax[k]-r*ax[k-1] + bwd-halo end-scan ----
    {
        float Bw = 0.f, E2 = 0.f;
        #pragma unroll
        for (int k = CL - 1; k >= 1; k--) {
            const float xk = fmaf(-r, ax[k - 1], ax[k]);   // scaled x_k
            Bw = fmaf(r, Bw, xk);                          // B_k
            E2 = fmaf(r, E2, bhx[k]);
            ax[k] = fmaf(r, ax[k - 1], Bw);                // t_k = r*F_{k-1} + B_k
        }
        Bw = fmaf(r, Bw, ax[0]);                 // x_0 = F_0 = ax[0]
        E2 = fmaf(r, E2, bhx[0]);
        ax[0] = Bw;                              // t_0 = B_0
        eb[w][lane] = Bw;                        // own bwd end (wc 8+w -> idx w)
        eb[8 + w][lane] = bh_ok ? E2 * scale : 0.f; // bwd halo end (idx 8+w)
    }

    __syncthreads();                             // the only barrier

    // ---- seeds: 8-term dot products over neighbor end-sums ----
    float s = 0.f, u = 0.f;
    {
        float rLd = 1.0f;
        #pragma unroll
        for (int d = 1; d <= HALOC; d++) {
            s = fmaf(ef[HALOC + w - d][lane], rLd, s);
            u = fmaf(eb[w + d][lane],         rLd, u);
            rLd *= rL;
        }
    }

    // ---- combine A (ascending): ax[k] += s*r^{k+1}, 4 interleaved *r^4 chains ----
    {
        float g0 = s * r, g1 = s * r2, g2 = s * r3, g3 = s * r4;
        #pragma unroll
        for (int j = 0; j < 8; j++) {
            const int k = 4 * j;
            ax[k + 0] += g0; g0 *= r4;
            ax[k + 1] += g1; g1 *= r4;
            ax[k + 2] += g2; g2 *= r4;
            ax[k + 3] += g3; g3 *= r4;
        }
    }

    // ---- combine B (descending) + store: out[k] = ax[k] + u*r^{32-k} ----
    float* op = out + ((size_t)b * NG + (size_t)(q * OUTC + w) * CL) * NCH + lane;
    {
        float h0 = u * r, h1 = u * r2, h2 = u * r3, h3 = u * r4;  // k=31,30,29,28
        #pragma unroll
        for (int j = 7; j >= 0; j--) {
            const int k = 4 * j;
            op[(size_t)(k + 3) * NCH] = ax[k + 3] + h0; h0 *= r4;
            op[(size_t)(k + 2) * NCH] = ax[k + 2] + h1; h1 *= r4;
            op[(size_t)(k + 1) * NCH] = ax[k + 1] + h2; h2 *= r4;
            op[(size_t)(k + 0) * NCH] = ax[k + 0] + h3; h3 *= r4;
        }
    }
}

extern "C" void kernel_launch(void* const* d_in, const int* in_sizes, int n_in,
                              void* d_out, int out_size)
{
    const float* x   = (const float*)d_in[0];  // inputs (32, 2048)
    // d_in[1] = grids (unused: uniform grid, spacing DX by construction)
    const float* eta = (const float*)d_in[2];  // eta (32,)
    float* out = (float*)d_out;                // (32, 2048, 32) fp32

    egc_kernel<<<NB * BPB, NTHREADS>>>(x, eta, out);
}

// round 12
// speedup vs baseline: 1.4251x; 1.4251x over previous
#include <cuda_runtime.h>

// ExponentialGlobalConv: out[b,m,c] = DX * sum_n x[b,n] * exp(-|n-m|*DX/w_c) / (2 w_c)
// Uniform grid => separable exponential kernel => fwd+bwd IIR scan.
// R12 = R9 (best measured: 8.35us bench / 6.46us kernel), reverted after R11's
// direct-LDG variant flooded the L1tex queue at 2 CTAs/SM (13.7us).
// 256-thread CTAs (8 warps), OUTC=8, grid=256, single wave, 2 CTAs/SM capable.
// The CTA window (3KB) is staged with one coalesced float4 per thread
// (zero-padded at row edges); all chunk reads are LDS broadcasts.
// Uniform warp roles: each warp scans its own chunk (fwd keeping Floc, bwd in
// place) and fuses one fwd-halo and one bwd-halo end-scan. Seeds = 8-term dot
// products over neighbor chunk end-sums (hop r^32); combine is 3 FMAs/element:
//   out[k] = fma(s, r^{k+1}, fma(u, r^{32-k}, fma(r, Floc[k-1], Bloc[k])))
// Halo truncation (HALOC=8 chunks) => rel_err ~1.9e-4 << 1e-3.

#define NCH   32
#define NG    2048
#define NB    32
#define DXC   0.08f
#define CL    32
#define HALOC 8                   // halo chunks per side
#define OUTC  8                   // output chunks per block
#define WINCH (OUTC + 2*HALOC)    // 24 window chunks
#define NWARP 8
#define NTHREADS (NWARP * 32)     // 256
#define BPB   8                   // blocks per batch row

__global__ __launch_bounds__(NTHREADS, 2)
void egc_kernel(const float* __restrict__ x,
                const float* __restrict__ eta,
                float* __restrict__ out)
{
    __shared__ float xs[WINCH * CL];   // 3KB zero-padded window, chunks baseg..baseg+23
    __shared__ float ef[16][32];       // fwd end-sums, window chunks 0..15
    __shared__ float eb[16][32];       // bwd end-sums, window chunks 8..23 (idx wc-8)

    const int tid  = threadIdx.x;
    const int lane = tid & 31;              // channel
    const int w    = tid >> 5;              // warp 0..7
    const int b    = blockIdx.x >> 3;       // batch row
    const int q    = blockIdx.x & 7;        // eighth of grid dim
    const int baseg = q * OUTC - HALOC;     // global chunk at window wc=0

    // ---- stage window into smem: threads 0..191 load one float4, zero-padded ----
    if (tid < WINCH * CL / 4) {
        const float4* xrow4 = reinterpret_cast<const float4*>(x + (size_t)b * NG);
        const int g4 = baseg * (CL / 4) + tid;          // global float4 index
        float4 v = make_float4(0.f, 0.f, 0.f, 0.f);
        if (g4 >= 0 && g4 < NG / 4) v = xrow4[g4];
        reinterpret_cast<float4*>(xs)[tid] = v;
    }

    // ---- per-channel params (under load shadow) ----
    const float e     = eta[lane];
    const float sig   = 1.0f / (1.0f + __expf(-e));
    const float wid   = 0.1f + 4.9f * sig;
    const float r     = __expf(-DXC / wid);
    const float scale = DXC / (2.0f * wid);
    const float r2 = r * r, r3 = r2 * r, r4 = r2 * r2;

    // power table rp[k] = r^{k+1} (no cross-warp deps)
    float rp[CL];
    rp[0] = r; rp[1] = r2; rp[2] = r3; rp[3] = r4;
    #pragma unroll
    for (int k = 4; k < CL; k++) rp[k] = rp[k - 4] * r4;
    const float rL = rp[31];                 // r^32

    __syncthreads();

    // ---- own chunk (window 8+w) into regs, pre-scaled ----
    float ax[CL];
    {
        const float4* pa = reinterpret_cast<const float4*>(xs + (HALOC + w) * CL);
        #pragma unroll
        for (int i = 0; i < 8; i++) reinterpret_cast<float4*>(ax)[i] = pa[i];
    }
    #pragma unroll
    for (int k = 0; k < CL; k++) ax[k] *= scale;

    // ---- pass 1: own fwd chain (keep Floc) + fwd-halo end-scan (window chunk w) ----
    float Floc[CL];
    {
        const float* hx = xs + w * CL;
        float F = 0.f, E = 0.f;
        #pragma unroll
        for (int k = 0; k < CL; k++) {
            F = fmaf(r, F, ax[k]); Floc[k] = F;
            E = fmaf(r, E, hx[k]);               // scalar LDS broadcast
        }
        ef[HALOC + w][lane] = F;                 // own fwd end (scaled)
        ef[w][lane] = E * scale;                 // fwd halo end
    }

    // ---- pass 2: own bwd chain in place (Bloc := ax) + bwd-halo end-scan (wc 16+w) ----
    {
        const float* hx = xs + (16 + w) * CL;
        float Bw = 0.f, E = 0.f;
        #pragma unroll
        for (int k = CL - 1; k >= 0; k--) {
            Bw = fmaf(r, Bw, ax[k]); ax[k] = Bw;
            E = fmaf(r, E, hx[k]);
        }
        eb[w][lane] = Bw;                        // own bwd end (wc 8+w -> idx w)
        eb[8 + w][lane] = E * scale;             // bwd halo end (wc 16+w -> idx 8+w)
    }

    __syncthreads();

    // ---- seeds: 8-term dot products over neighbor end-sums ----
    float s = 0.f, u = 0.f;
    {
        float rLd = 1.0f;
        #pragma unroll
        for (int d = 1; d <= HALOC; d++) {
            s = fmaf(ef[HALOC + w - d][lane], rLd, s);
            u = fmaf(eb[w + d][lane],         rLd, u);
            rLd *= rL;
        }
    }

    // ---- combine + store: 3 independent FMAs per element ----
    float* op = out + ((size_t)b * NG + (size_t)(q * OUTC + w) * CL) * NCH + lane;
    op[0] = fmaf(s, rp[0], fmaf(u, rp[31], ax[0]));
    #pragma unroll
    for (int k = 1; k < CL; k++) {
        const float t = fmaf(r, Floc[k - 1], ax[k]);
        op[(size_t)k * NCH] = fmaf(s, rp[k], fmaf(u, rp[31 - k], t));
    }
}

extern "C" void kernel_launch(void* const* d_in, const int* in_sizes, int n_in,
                              void* d_out, int out_size)
{
    const float* x   = (const float*)d_in[0];  // inputs (32, 2048)
    // d_in[1] = grids (unused: uniform grid, spacing DX by construction)
    const float* eta = (const float*)d_in[2];  // eta (32,)
    float* out = (float*)d_out;                // (32, 2048, 32) fp32

    egc_kernel<<<NB * BPB, NTHREADS>>>(x, eta, out);
}

// round 13
// speedup vs baseline: 1.5261x; 1.0709x over previous
#include <cuda_runtime.h>

// ExponentialGlobalConv: out[b,m,c] = DX * sum_n x[b,n] * exp(-|n-m|*DX/w_c) / (2 w_c)
// Uniform grid => separable exponential (Laplace) kernel => fwd+bwd IIR scan:
//   S_f[m] = x[m] + r*S_f[m-1], S_b[m] = x[m] + r*S_b[m+1], r = exp(-DX/w)
//   out[m] = scale*(S_f[m] + S_b[m] - x[m]),  scale = DX/(2w)
//
// FINAL (R13 = best measured config, kernel 6.43us):
// - 256 CTAs x 256 threads (8 warps), single wave, 2 CTAs/SM capable.
// - CTA stages its 24-chunk window (3KB) with one coalesced float4/thread
//   (zero-padded at row edges); all chunk reads are LDS broadcasts (lane=channel).
// - Uniform warp roles: each warp scans its own output chunk (fwd keeping Floc,
//   bwd in place) and fuses one fwd-halo + one bwd-halo end-only scan.
// - Seeds s,u = 8-term dot products over neighbor chunk end-sums (hop r^32).
// - Combine = 3 independent FMAs per element:
//     out[k] = fma(s, r^{k+1}, fma(u, r^{32-k}, fma(r, Floc[k-1], Bloc[k])))
// - Halo truncation (HALOC=8 chunks ~ e^{-8} relative) => rel_err 1.95e-4 << 1e-3.
// Session evidence: kernel is pinned at a ~5000-cycle launch/ramp floor; all
// pipes <13%, output drain through L2 ~0.85us. Structural variants (direct LDG,
// register-light, 2-wave, 512-thr) were neutral or regressions.

#define NCH   32
#define NG    2048
#define NB    32
#define DXC   0.08f
#define CL    32
#define HALOC 8                   // halo chunks per side
#define OUTC  8                   // output chunks per block
#define WINCH (OUTC + 2*HALOC)    // 24 window chunks
#define NWARP 8
#define NTHREADS (NWARP * 32)     // 256
#define BPB   8                   // blocks per batch row

__global__ __launch_bounds__(NTHREADS, 2)
void egc_kernel(const float* __restrict__ x,
                const float* __restrict__ eta,
                float* __restrict__ out)
{
    __shared__ float xs[WINCH * CL];   // 3KB zero-padded window, chunks baseg..baseg+23
    __shared__ float ef[16][32];       // fwd end-sums, window chunks 0..15
    __shared__ float eb[16][32];       // bwd end-sums, window chunks 8..23 (idx wc-8)

    const int tid  = threadIdx.x;
    const int lane = tid & 31;              // channel
    const int w    = tid >> 5;              // warp 0..7
    const int b    = blockIdx.x >> 3;       // batch row
    const int q    = blockIdx.x & 7;        // eighth of grid dim
    const int baseg = q * OUTC - HALOC;     // global chunk at window wc=0

    // ---- stage window into smem: threads 0..191 load one float4, zero-padded ----
    if (tid < WINCH * CL / 4) {
        const float4* xrow4 = reinterpret_cast<const float4*>(x + (size_t)b * NG);
        const int g4 = baseg * (CL / 4) + tid;          // global float4 index
        float4 v = make_float4(0.f, 0.f, 0.f, 0.f);
        if (g4 >= 0 && g4 < NG / 4) v = xrow4[g4];
        reinterpret_cast<float4*>(xs)[tid] = v;
    }

    // ---- per-channel params (under load shadow) ----
    const float e     = eta[lane];
    const float sig   = 1.0f / (1.0f + __expf(-e));
    const float wid   = 0.1f + 4.9f * sig;
    const float r     = __expf(-DXC / wid);
    const float scale = DXC / (2.0f * wid);
    const float r2 = r * r, r3 = r2 * r, r4 = r2 * r2;

    // power table rp[k] = r^{k+1} (no cross-warp deps)
    float rp[CL];
    rp[0] = r; rp[1] = r2; rp[2] = r3; rp[3] = r4;
    #pragma unroll
    for (int k = 4; k < CL; k++) rp[k] = rp[k - 4] * r4;
    const float rL = rp[31];                 // r^32

    __syncthreads();

    // ---- own chunk (window 8+w) into regs, pre-scaled ----
    float ax[CL];
    {
        const float4* pa = reinterpret_cast<const float4*>(xs + (HALOC + w) * CL);
        #pragma unroll
        for (int i = 0; i < 8; i++) reinterpret_cast<float4*>(ax)[i] = pa[i];
    }
    #pragma unroll
    for (int k = 0; k < CL; k++) ax[k] *= scale;

    // ---- pass 1: own fwd chain (keep Floc) + fwd-halo end-scan (window chunk w) ----
    float Floc[CL];
    {
        const float* hx = xs + w * CL;
        float F = 0.f, E = 0.f;
        #pragma unroll
        for (int k = 0; k < CL; k++) {
            F = fmaf(r, F, ax[k]); Floc[k] = F;
            E = fmaf(r, E, hx[k]);               // scalar LDS broadcast
        }
        ef[HALOC + w][lane] = F;                 // own fwd end (scaled)
        ef[w][lane] = E * scale;                 // fwd halo end
    }

    // ---- pass 2: own bwd chain in place (Bloc := ax) + bwd-halo end-scan (wc 16+w) ----
    {
        const float* hx = xs + (16 + w) * CL;
        float Bw = 0.f, E = 0.f;
        #pragma unroll
        for (int k = CL - 1; k >= 0; k--) {
            Bw = fmaf(r, Bw, ax[k]); ax[k] = Bw;
            E = fmaf(r, E, hx[k]);
        }
        eb[w][lane] = Bw;                        // own bwd end (wc 8+w -> idx w)
        eb[8 + w][lane] = E * scale;             // bwd halo end (wc 16+w -> idx 8+w)
    }

    __syncthreads();

    // ---- seeds: 8-term dot products over neighbor end-sums ----
    float s = 0.f, u = 0.f;
    {
        float rLd = 1.0f;
        #pragma unroll
        for (int d = 1; d <= HALOC; d++) {
            s = fmaf(ef[HALOC + w - d][lane], rLd, s);
            u = fmaf(eb[w + d][lane],         rLd, u);
            rLd *= rL;
        }
    }

    // ---- combine + store: 3 independent FMAs per element ----
    float* op = out + ((size_t)b * NG + (size_t)(q * OUTC + w) * CL) * NCH + lane;
    op[0] = fmaf(s, rp[0], fmaf(u, rp[31], ax[0]));
    #pragma unroll
    for (int k = 1; k < CL; k++) {
        const float t = fmaf(r, Floc[k - 1], ax[k]);
        op[(size_t)k * NCH] = fmaf(s, rp[k], fmaf(u, rp[31 - k], t));
    }
}

extern "C" void kernel_launch(void* const* d_in, const int* in_sizes, int n_in,
                              void* d_out, int out_size)
{
    const float* x   = (const float*)d_in[0];  // inputs (32, 2048)
    // d_in[1] = grids (unused: uniform grid, spacing DX by construction)
    const float* eta = (const float*)d_in[2];  // eta (32,)
    float* out = (float*)d_out;                // (32, 2048, 32) fp32

    egc_kernel<<<NB * BPB, NTHREADS>>>(x, eta, out);
}